// round 1
// baseline (speedup 1.0000x reference)
#include <cuda_runtime.h>
#include <math.h>

// Problem constants (verified against reference: N=100000, E=1600000, EL=1000000,
// F=64, S=64, C=32). Runtime sizes are derived from in_sizes for the guards.
#define MAXN 100000

// -------- scratch (device globals; no allocations allowed) --------
__device__ float g_h   [MAXN * 64];  // LSTM output h, later reused for h2 (relu layer-1 out)
__device__ float g_hw1 [MAXN * 64];  // h  @ W1
__device__ float g_out1[MAXN * 64];  // layer-1 scatter accumulator
__device__ float g_hw2 [MAXN * 32];  // h2 @ W2
__device__ float g_out2[MAXN * 32];  // layer-2 scatter accumulator -> z (in place)
__device__ float g_deg [MAXN];
__device__ float g_dinv[MAXN];

// Vectorized global float atomic add (sm_90+): one L2 atomic op per 4 floats.
__device__ __forceinline__ void red_add_v4(float* p, float4 v) {
    asm volatile("red.global.add.v4.f32 [%0], {%1,%2,%3,%4};"
                 :: "l"(p), "f"(v.x), "f"(v.y), "f"(v.z), "f"(v.w)
                 : "memory");
}

// -------- init: zero accumulators, deg = 1 (self loop) --------
__global__ void k_init(int n) {
    int i = blockIdx.x * blockDim.x + threadIdx.x;
    float4 z = make_float4(0.f, 0.f, 0.f, 0.f);
    if (i < n * 16) ((float4*)g_out1)[i] = z;
    if (i < n * 8)  ((float4*)g_out2)[i] = z;
    if (i < n)      g_deg[i] = 1.0f;
}

// -------- degree count over col --------
__global__ void k_deg(const int* __restrict__ col, int E) {
    int i = blockIdx.x * blockDim.x + threadIdx.x;
    if (i < E) atomicAdd(&g_deg[col[i]], 1.0f);
}

__global__ void k_dinv(int n) {
    int i = blockIdx.x * blockDim.x + threadIdx.x;
    if (i < n) g_dinv[i] = rsqrtf(g_deg[i]);
}

// -------- LSTM step (f gate dead: c0=0). h = sigmoid(o)*tanh(sigmoid(i)*tanh(g)) ---
// One row per thread; x row in registers; W_ih gate blocks (i,g,o) in shared (48KB).
__global__ void __launch_bounds__(128) k_lstm(
    const float* __restrict__ x, const float* __restrict__ Wih,
    const float* __restrict__ bih, const float* __restrict__ bhh, int n)
{
    __shared__ float sw[3 * 4096];  // 48KB: rows [0:64)=i, [128:192)=g, [192:256)=o
    for (int idx = threadIdx.x; idx < 4096; idx += 128) {
        sw[idx]          = Wih[idx];             // i block
        sw[4096 + idx]   = Wih[128 * 64 + idx];  // g block
        sw[8192 + idx]   = Wih[192 * 64 + idx];  // o block
    }
    __syncthreads();

    int r = blockIdx.x * 128 + threadIdx.x;
    if (r >= n) return;

    float4 xv[16];
    const float4* xr = (const float4*)(x + (size_t)r * 64);
#pragma unroll
    for (int k = 0; k < 16; k++) xv[k] = xr[k];

    const float4* swi = (const float4*)sw;
    const float4* swg = (const float4*)(sw + 4096);
    const float4* swo = (const float4*)(sw + 8192);
    float* hout = g_h + (size_t)r * 64;

    for (int j = 0; j < 64; j++) {
        float ai = bih[j]       + bhh[j];
        float ag = bih[128 + j] + bhh[128 + j];
        float ao = bih[192 + j] + bhh[192 + j];
#pragma unroll
        for (int k = 0; k < 16; k++) {
            float4 xk = xv[k];
            float4 wi = swi[j * 16 + k];
            float4 wg = swg[j * 16 + k];
            float4 wo = swo[j * 16 + k];
            ai = fmaf(xk.x, wi.x, ai); ai = fmaf(xk.y, wi.y, ai);
            ai = fmaf(xk.z, wi.z, ai); ai = fmaf(xk.w, wi.w, ai);
            ag = fmaf(xk.x, wg.x, ag); ag = fmaf(xk.y, wg.y, ag);
            ag = fmaf(xk.z, wg.z, ag); ag = fmaf(xk.w, wg.w, ag);
            ao = fmaf(xk.x, wo.x, ao); ao = fmaf(xk.y, wo.y, ao);
            ao = fmaf(xk.z, wo.z, ao); ao = fmaf(xk.w, wo.w, ao);
        }
        float si = 1.0f / (1.0f + expf(-ai));
        float so = 1.0f / (1.0f + expf(-ao));
        float c  = si * tanhf(ag);
        hout[j]  = so * tanhf(c);
    }
}

// -------- Out[n, JOUT] = Hin[n, 64] @ W[64, JOUT]; W transposed into shared ------
template <int JOUT>
__global__ void __launch_bounds__(128) k_gemm(
    const float* __restrict__ Hin, const float* __restrict__ W,
    float* __restrict__ Out, int n)
{
    __shared__ float swt[JOUT * 64];  // swt[j*64 + k] = W[k*JOUT + j]
    for (int idx = threadIdx.x; idx < JOUT * 64; idx += 128) {
        int k = idx / JOUT, j = idx % JOUT;
        swt[j * 64 + k] = W[idx];
    }
    __syncthreads();

    int r = blockIdx.x * 128 + threadIdx.x;
    if (r >= n) return;

    float4 hv[16];
    const float4* hr = (const float4*)(Hin + (size_t)r * 64);
#pragma unroll
    for (int k = 0; k < 16; k++) hv[k] = hr[k];

    const float4* sw4 = (const float4*)swt;
    for (int j = 0; j < JOUT; j++) {
        float acc = 0.f;
#pragma unroll
        for (int k = 0; k < 16; k++) {
            float4 w = sw4[j * 16 + k];
            float4 h = hv[k];
            acc = fmaf(h.x, w.x, acc); acc = fmaf(h.y, w.y, acc);
            acc = fmaf(h.z, w.z, acc); acc = fmaf(h.w, w.w, acc);
        }
        Out[(size_t)r * JOUT + j] = acc;
    }
}

// -------- edge scatter: Out[col] += dinv[row]*dinv[col] * HW[row] (V float4/row) --
template <int V>
__global__ void k_scatter(const int* __restrict__ row, const int* __restrict__ col,
                          const float* __restrict__ HW, float* __restrict__ Out, int E)
{
    int gid = blockIdx.x * blockDim.x + threadIdx.x;
    if (gid >= E * V) return;
    int e = gid / V;
    int j = gid % V;
    int r = row[e], c = col[e];
    float w = g_dinv[r] * g_dinv[c];
    float4 v = ((const float4*)HW)[(size_t)r * V + j];
    v.x *= w; v.y *= w; v.z *= w; v.w *= w;
    red_add_v4(Out + (size_t)c * (V * 4) + j * 4, v);
}

// -------- epilogue: Out = [relu](Acc + dinv^2 * HW + bias) --------
template <int V, bool RELU>
__global__ void k_finish(const float* __restrict__ Acc, const float* __restrict__ HW,
                         const float* __restrict__ bias, float* __restrict__ Out, int n)
{
    int gid = blockIdx.x * blockDim.x + threadIdx.x;
    if (gid >= n * V) return;
    int r = gid / V;
    int j = gid % V;
    float di = g_dinv[r];
    float sl = di * di;
    float4 a = ((const float4*)Acc)[gid];
    float4 h = ((const float4*)HW)[gid];
    float4 b = ((const float4*)bias)[j];
    float4 o;
    o.x = a.x + sl * h.x + b.x;
    o.y = a.y + sl * h.y + b.y;
    o.z = a.z + sl * h.z + b.z;
    o.w = a.w + sl * h.w + b.w;
    if (RELU) {
        o.x = fmaxf(o.x, 0.f); o.y = fmaxf(o.y, 0.f);
        o.z = fmaxf(o.z, 0.f); o.w = fmaxf(o.w, 0.f);
    }
    ((float4*)Out)[gid] = o;
}

// -------- edge dot: out[e] = dot(z[src], z[dst]) over 32 feats; 8 lanes/edge -----
// NOTE: EL*8 is an exact multiple of 256 (EL=1e6), so no partial warps reach shfl.
__global__ void k_edot(const int* __restrict__ eli, float* __restrict__ out, int EL)
{
    int gid = blockIdx.x * blockDim.x + threadIdx.x;
    if (gid >= EL * 8) return;
    int e = gid >> 3;
    int j = gid & 7;
    int s = eli[e];
    int d = eli[EL + e];
    float4 a = ((const float4*)g_out2)[(size_t)s * 8 + j];
    float4 b = ((const float4*)g_out2)[(size_t)d * 8 + j];
    float p = a.x * b.x + a.y * b.y + a.z * b.z + a.w * b.w;
    p += __shfl_down_sync(0xffffffffu, p, 4);
    p += __shfl_down_sync(0xffffffffu, p, 2);
    p += __shfl_down_sync(0xffffffffu, p, 1);
    if (j == 0) out[e] = p;
}

extern "C" void kernel_launch(void* const* d_in, const int* in_sizes, int n_in,
                              void* d_out, int out_size)
{
    (void)n_in; (void)out_size;
    const float* x   = (const float*)d_in[0];
    const int*   ei  = (const int*)  d_in[1];
    const int*   eli = (const int*)  d_in[2];
    const float* Wih = (const float*)d_in[3];
    // d_in[4] = W_hh: unused (h0 = 0)
    const float* bih = (const float*)d_in[5];
    const float* bhh = (const float*)d_in[6];
    const float* W1  = (const float*)d_in[7];
    const float* b1  = (const float*)d_in[8];
    const float* W2  = (const float*)d_in[9];
    const float* b2  = (const float*)d_in[10];
    float* out = (float*)d_out;

    int n  = in_sizes[0] / 64;
    int E  = in_sizes[1] / 2;
    int EL = in_sizes[2] / 2;
    const int* row = ei;
    const int* col = ei + E;

    // Resolve scratch symbol addresses (host-side API; not a stream op, capture-safe)
    float *p_h, *p_hw1, *p_out1, *p_hw2, *p_out2;
    cudaGetSymbolAddress((void**)&p_h,    g_h);
    cudaGetSymbolAddress((void**)&p_hw1,  g_hw1);
    cudaGetSymbolAddress((void**)&p_out1, g_out1);
    cudaGetSymbolAddress((void**)&p_hw2,  g_hw2);
    cudaGetSymbolAddress((void**)&p_out2, g_out2);

    const int T = 256;

    k_init<<<(n * 16 + T - 1) / T, T>>>(n);
    k_deg <<<(E + T - 1) / T, T>>>(col, E);
    k_dinv<<<(n + T - 1) / T, T>>>(n);

    k_lstm<<<(n + 127) / 128, 128>>>(x, Wih, bih, bhh, n);
    k_gemm<64><<<(n + 127) / 128, 128>>>(p_h, W1, p_hw1, n);

    k_scatter<16><<<(E * 16 + T - 1) / T, T>>>(row, col, p_hw1, p_out1, E);
    k_finish<16, true><<<(n * 16 + T - 1) / T, T>>>(p_out1, p_hw1, b1, p_h, n);

    k_gemm<32><<<(n + 127) / 128, 128>>>(p_h, W2, p_hw2, n);
    k_scatter<8><<<(E * 8 + T - 1) / T, T>>>(row, col, p_hw2, p_out2, E);
    k_finish<8, false><<<(n * 8 + T - 1) / T, T>>>(p_out2, p_hw2, b2, p_out2, n);

    k_edot<<<(EL * 8 + T - 1) / T, T>>>(eli, out, EL);
}

// round 2
// speedup vs baseline: 1.1805x; 1.1805x over previous
#include <cuda_runtime.h>
#include <math.h>

#define MAXN 100000

// -------- scratch (device globals; no allocations allowed) --------
__device__ float g_h   [MAXN * 64];  // LSTM output h, later reused for h2 (relu layer-1 out)
__device__ float g_hw1 [MAXN * 64];  // h  @ W1
__device__ float g_out1[MAXN * 64];  // layer-1 scatter accumulator
__device__ float g_hw2 [MAXN * 32];  // h2 @ W2
__device__ float g_out2[MAXN * 32];  // layer-2 scatter accumulator -> z (in place)
__device__ float g_deg [MAXN];
__device__ float g_dinv[MAXN];

__device__ __forceinline__ void red_add_v4(float* p, float4 v) {
    asm volatile("red.global.add.v4.f32 [%0], {%1,%2,%3,%4};"
                 :: "l"(p), "f"(v.x), "f"(v.y), "f"(v.z), "f"(v.w)
                 : "memory");
}

// -------- init / degree / dinv --------
__global__ void k_init(int n) {
    int i = blockIdx.x * blockDim.x + threadIdx.x;
    float4 z = make_float4(0.f, 0.f, 0.f, 0.f);
    if (i < n * 16) ((float4*)g_out1)[i] = z;
    if (i < n * 8)  ((float4*)g_out2)[i] = z;
    if (i < n)      g_deg[i] = 1.0f;
}

__global__ void k_deg(const int* __restrict__ col, int E) {
    int i = blockIdx.x * blockDim.x + threadIdx.x;
    if (i < E) atomicAdd(&g_deg[col[i]], 1.0f);
}

__global__ void k_dinv(int n) {
    int i = blockIdx.x * blockDim.x + threadIdx.x;
    if (i < n) g_dinv[i] = rsqrtf(g_deg[i]);
}

// ===================== register-tiled LSTM GEMM ============================
// gates = x @ W_ih.T (+biases); only i,g,o blocks needed (f dead since c0=0).
// Block: 64 rows x 64 j. 256 threads, each 8 rows x 2 j x 3 gates = 48 accs.
// xs[k][row] transposed (pad 68 => 272B rows, 16B aligned, conflict-free reads).
__global__ void __launch_bounds__(256) k_lstm(
    const float* __restrict__ x, const float* __restrict__ Wih,
    const float* __restrict__ bih, const float* __restrict__ bhh, int n)
{
    __shared__ float xs[32][68];
    __shared__ float ws[32][192];   // ws[k][g*64+j], gates i,g,o

    const int t  = threadIdx.x;
    const int br = blockIdx.x * 64;
    const int rg = t & 7,  jg = t >> 3;
    const int r0 = rg * 8, j0 = jg * 2;

    float acc[3][2][8];
#pragma unroll
    for (int g = 0; g < 3; g++)
#pragma unroll
        for (int jj = 0; jj < 2; jj++)
#pragma unroll
            for (int r = 0; r < 8; r++) acc[g][jj][r] = 0.f;

#pragma unroll
    for (int kc = 0; kc < 64; kc += 32) {
        if (kc) __syncthreads();
        // x tile: 64 rows x 32 k, store transposed
#pragma unroll
        for (int p = 0; p < 2; p++) {
            int l4 = p * 256 + t;           // 0..511
            int kq = l4 & 7, row = l4 >> 3; // kq: float4 along k, row 0..63
            float4 v = make_float4(0.f, 0.f, 0.f, 0.f);
            if (br + row < n)
                v = ((const float4*)x)[(size_t)(br + row) * 16 + (kc >> 2) + kq];
            xs[4 * kq + 0][row] = v.x; xs[4 * kq + 1][row] = v.y;
            xs[4 * kq + 2][row] = v.z; xs[4 * kq + 3][row] = v.w;
        }
        // weights: 3 gates x 64 j x 32 k = 1536 float4
#pragma unroll
        for (int p = 0; p < 6; p++) {
            int l4 = p * 256 + t;           // 0..1535
            int j  = l4 & 63;
            int gk = l4 >> 6;               // 0..23
            int g  = gk % 3;
            int kq = gk / 3;                // 0..7
            int goff = (g == 0) ? 0 : (g == 1 ? 128 : 192);
            float4 v = ((const float4*)Wih)[(size_t)(goff + j) * 16 + (kc >> 2) + kq];
            ws[4 * kq + 0][g * 64 + j] = v.x; ws[4 * kq + 1][g * 64 + j] = v.y;
            ws[4 * kq + 2][g * 64 + j] = v.z; ws[4 * kq + 3][g * 64 + j] = v.w;
        }
        __syncthreads();

#pragma unroll
        for (int k = 0; k < 32; k++) {
            float4 xa = *(const float4*)&xs[k][r0];
            float4 xb = *(const float4*)&xs[k][r0 + 4];
            float2 wi = *(const float2*)&ws[k][j0];
            float2 wg = *(const float2*)&ws[k][64 + j0];
            float2 wo = *(const float2*)&ws[k][128 + j0];
            float xv[8] = {xa.x, xa.y, xa.z, xa.w, xb.x, xb.y, xb.z, xb.w};
            float wv[3][2] = {{wi.x, wi.y}, {wg.x, wg.y}, {wo.x, wo.y}};
#pragma unroll
            for (int g = 0; g < 3; g++)
#pragma unroll
                for (int jj = 0; jj < 2; jj++)
#pragma unroll
                    for (int r = 0; r < 8; r++)
                        acc[g][jj][r] = fmaf(wv[g][jj], xv[r], acc[g][jj][r]);
        }
    }

#pragma unroll
    for (int jj = 0; jj < 2; jj++) {
        int j = j0 + jj;
        float bi = bih[j]       + bhh[j];
        float bg = bih[128 + j] + bhh[128 + j];
        float bo = bih[192 + j] + bhh[192 + j];
#pragma unroll
        for (int r = 0; r < 8; r++) {
            int row = br + r0 + r;
            if (row < n) {
                float ai = acc[0][jj][r] + bi;
                float ag = acc[1][jj][r] + bg;
                float ao = acc[2][jj][r] + bo;
                float si = 1.0f / (1.0f + expf(-ai));
                float so = 1.0f / (1.0f + expf(-ao));
                float c  = si * tanhf(ag);
                g_h[(size_t)row * 64 + j] = so * tanhf(c);
            }
        }
    }
}

// ===================== register-tiled GEMM, JOUT=64 ========================
// Block: 64 rows x 64 j; 128 threads, each 8 rows x 4 j.
__global__ void __launch_bounds__(128) k_gemm64(
    const float* __restrict__ H, const float* __restrict__ W,
    float* __restrict__ Out, int n)
{
    __shared__ float xs[64][68];
    __shared__ float ws[64][64];   // same layout as W (row-major [k][j])

    const int t  = threadIdx.x;
    const int br = blockIdx.x * 64;
    const int rg = t & 7,  jg = t >> 3;   // jg 0..15
    const int r0 = rg * 8, j0 = jg * 4;

    float acc[4][8];
#pragma unroll
    for (int jj = 0; jj < 4; jj++)
#pragma unroll
        for (int r = 0; r < 8; r++) acc[jj][r] = 0.f;

#pragma unroll
    for (int p = 0; p < 8; p++) {
        int l4 = p * 128 + t;            // 0..1023
        int kq = l4 & 15, row = l4 >> 4;
        float4 v = make_float4(0.f, 0.f, 0.f, 0.f);
        if (br + row < n) v = ((const float4*)H)[(size_t)(br + row) * 16 + kq];
        xs[4 * kq + 0][row] = v.x; xs[4 * kq + 1][row] = v.y;
        xs[4 * kq + 2][row] = v.z; xs[4 * kq + 3][row] = v.w;
    }
#pragma unroll
    for (int p = 0; p < 8; p++) {
        int l4 = p * 128 + t;
        ((float4*)ws)[l4] = ((const float4*)W)[l4];
    }
    __syncthreads();

#pragma unroll
    for (int k = 0; k < 64; k++) {
        float4 xa = *(const float4*)&xs[k][r0];
        float4 xb = *(const float4*)&xs[k][r0 + 4];
        float4 w  = *(const float4*)&ws[k][j0];
        float xv[8] = {xa.x, xa.y, xa.z, xa.w, xb.x, xb.y, xb.z, xb.w};
        float wv[4] = {w.x, w.y, w.z, w.w};
#pragma unroll
        for (int jj = 0; jj < 4; jj++)
#pragma unroll
            for (int r = 0; r < 8; r++)
                acc[jj][r] = fmaf(wv[jj], xv[r], acc[jj][r]);
    }

#pragma unroll
    for (int r = 0; r < 8; r++) {
        int row = br + r0 + r;
        if (row < n) {
            float4 o = make_float4(acc[0][r], acc[1][r], acc[2][r], acc[3][r]);
            ((float4*)Out)[(size_t)row * 16 + (j0 >> 2)] = o;
        }
    }
}

// ===================== register-tiled GEMM, JOUT=32 ========================
// Block: 128 rows x 32 j; 256 threads, each 8 rows x 2 j.
__global__ void __launch_bounds__(256) k_gemm32(
    const float* __restrict__ H, const float* __restrict__ W,
    float* __restrict__ Out, int n)
{
    __shared__ float xs[64][132];
    __shared__ float ws[64][32];

    const int t  = threadIdx.x;
    const int br = blockIdx.x * 128;
    const int rg = t & 15, jg = t >> 4;   // jg 0..15
    const int r0 = rg * 8, j0 = jg * 2;

    float acc[2][8];
#pragma unroll
    for (int jj = 0; jj < 2; jj++)
#pragma unroll
        for (int r = 0; r < 8; r++) acc[jj][r] = 0.f;

#pragma unroll
    for (int p = 0; p < 8; p++) {
        int l4 = p * 256 + t;            // 0..2047
        int kq = l4 & 15, row = l4 >> 4; // row 0..127
        float4 v = make_float4(0.f, 0.f, 0.f, 0.f);
        if (br + row < n) v = ((const float4*)H)[(size_t)(br + row) * 16 + kq];
        xs[4 * kq + 0][row] = v.x; xs[4 * kq + 1][row] = v.y;
        xs[4 * kq + 2][row] = v.z; xs[4 * kq + 3][row] = v.w;
    }
#pragma unroll
    for (int p = 0; p < 2; p++) {
        int l4 = p * 256 + t;            // 0..511
        ((float4*)ws)[l4] = ((const float4*)W)[l4];
    }
    __syncthreads();

#pragma unroll
    for (int k = 0; k < 64; k++) {
        float4 xa = *(const float4*)&xs[k][r0];
        float4 xb = *(const float4*)&xs[k][r0 + 4];
        float2 w  = *(const float2*)&ws[k][j0];
        float xv[8] = {xa.x, xa.y, xa.z, xa.w, xb.x, xb.y, xb.z, xb.w};
        float wv[2] = {w.x, w.y};
#pragma unroll
        for (int jj = 0; jj < 2; jj++)
#pragma unroll
            for (int r = 0; r < 8; r++)
                acc[jj][r] = fmaf(wv[jj], xv[r], acc[jj][r]);
    }

#pragma unroll
    for (int r = 0; r < 8; r++) {
        int row = br + r0 + r;
        if (row < n) {
            float2 o = make_float2(acc[0][r], acc[1][r]);
            ((float2*)Out)[(size_t)row * 16 + jg] = o;
        }
    }
}

// -------- edge scatter: Out[col] += dinv[row]*dinv[col] * HW[row] ---------
template <int V>
__global__ void k_scatter(const int* __restrict__ row, const int* __restrict__ col,
                          const float* __restrict__ HW, float* __restrict__ Out, int E)
{
    int gid = blockIdx.x * blockDim.x + threadIdx.x;
    if (gid >= E * V) return;
    int e = gid / V;
    int j = gid % V;
    int r = row[e], c = col[e];
    float w = g_dinv[r] * g_dinv[c];
    float4 v = ((const float4*)HW)[(size_t)r * V + j];
    v.x *= w; v.y *= w; v.z *= w; v.w *= w;
    red_add_v4(Out + (size_t)c * (V * 4) + j * 4, v);
}

// -------- epilogue: Out = [relu](Acc + dinv^2 * HW + bias) --------
template <int V, bool RELU>
__global__ void k_finish(const float* __restrict__ Acc, const float* __restrict__ HW,
                         const float* __restrict__ bias, float* __restrict__ Out, int n)
{
    int gid = blockIdx.x * blockDim.x + threadIdx.x;
    if (gid >= n * V) return;
    int r = gid / V;
    int j = gid % V;
    float di = g_dinv[r];
    float sl = di * di;
    float4 a = ((const float4*)Acc)[gid];
    float4 h = ((const float4*)HW)[gid];
    float4 b = ((const float4*)bias)[j];
    float4 o;
    o.x = a.x + sl * h.x + b.x;
    o.y = a.y + sl * h.y + b.y;
    o.z = a.z + sl * h.z + b.z;
    o.w = a.w + sl * h.w + b.w;
    if (RELU) {
        o.x = fmaxf(o.x, 0.f); o.y = fmaxf(o.y, 0.f);
        o.z = fmaxf(o.z, 0.f); o.w = fmaxf(o.w, 0.f);
    }
    ((float4*)Out)[gid] = o;
}

// -------- edge dot --------
__global__ void k_edot(const int* __restrict__ eli, float* __restrict__ out, int EL)
{
    int gid = blockIdx.x * blockDim.x + threadIdx.x;
    if (gid >= EL * 8) return;
    int e = gid >> 3;
    int j = gid & 7;
    int s = eli[e];
    int d = eli[EL + e];
    float4 a = ((const float4*)g_out2)[(size_t)s * 8 + j];
    float4 b = ((const float4*)g_out2)[(size_t)d * 8 + j];
    float p = a.x * b.x + a.y * b.y + a.z * b.z + a.w * b.w;
    p += __shfl_down_sync(0xffffffffu, p, 4);
    p += __shfl_down_sync(0xffffffffu, p, 2);
    p += __shfl_down_sync(0xffffffffu, p, 1);
    if (j == 0) out[e] = p;
}

extern "C" void kernel_launch(void* const* d_in, const int* in_sizes, int n_in,
                              void* d_out, int out_size)
{
    (void)n_in; (void)out_size;
    const float* x   = (const float*)d_in[0];
    const int*   ei  = (const int*)  d_in[1];
    const int*   eli = (const int*)  d_in[2];
    const float* Wih = (const float*)d_in[3];
    const float* bih = (const float*)d_in[5];
    const float* bhh = (const float*)d_in[6];
    const float* W1  = (const float*)d_in[7];
    const float* b1  = (const float*)d_in[8];
    const float* W2  = (const float*)d_in[9];
    const float* b2  = (const float*)d_in[10];
    float* out = (float*)d_out;

    int n  = in_sizes[0] / 64;
    int E  = in_sizes[1] / 2;
    int EL = in_sizes[2] / 2;
    const int* row = ei;
    const int* col = ei + E;

    float *p_h, *p_hw1, *p_out1, *p_hw2, *p_out2;
    cudaGetSymbolAddress((void**)&p_h,    g_h);
    cudaGetSymbolAddress((void**)&p_hw1,  g_hw1);
    cudaGetSymbolAddress((void**)&p_out1, g_out1);
    cudaGetSymbolAddress((void**)&p_hw2,  g_hw2);
    cudaGetSymbolAddress((void**)&p_out2, g_out2);

    const int T = 256;

    k_init<<<(n * 16 + T - 1) / T, T>>>(n);
    k_deg <<<(E + T - 1) / T, T>>>(col, E);
    k_dinv<<<(n + T - 1) / T, T>>>(n);

    k_lstm<<<(n + 63) / 64, 256>>>(x, Wih, bih, bhh, n);
    k_gemm64<<<(n + 63) / 64, 128>>>(p_h, W1, p_hw1, n);

    k_scatter<16><<<(E * 16 + T - 1) / T, T>>>(row, col, p_hw1, p_out1, E);
    k_finish<16, true><<<(n * 16 + T - 1) / T, T>>>(p_out1, p_hw1, b1, p_h, n);

    k_gemm32<<<(n + 127) / 128, 256>>>(p_h, W2, p_hw2, n);
    k_scatter<8><<<(E * 8 + T - 1) / T, T>>>(row, col, p_hw2, p_out2, E);
    k_finish<8, false><<<(n * 8 + T - 1) / T, T>>>(p_out2, p_hw2, b2, p_out2, n);

    k_edot<<<(EL * 8 + T - 1) / T, T>>>(eli, out, EL);
}

// round 3
// speedup vs baseline: 1.6569x; 1.4036x over previous
#include <cuda_runtime.h>
#include <math.h>

#define MAXN 100000
#define MAXE 1600000

// -------- scratch (device globals; no allocations allowed) --------
__device__ float g_h   [MAXN * 64];  // LSTM out h; later relu(conv1) out
__device__ float g_hw1 [MAXN * 64];  // h  @ W1
__device__ float g_hw2 [MAXN * 32];  // h2 @ W2
__device__ float g_z   [MAXN * 32];  // conv2 out
__device__ float g_dinv[MAXN];
__device__ int   g_cnt [MAXN];       // in-degree (no self loop)
__device__ int   g_start[MAXN];      // CSR exclusive offsets
__device__ int   g_cur [MAXN];       // fill cursors
__device__ int   g_adj [MAXE];       // CSR: source node per in-edge
__device__ int   g_bsum[256];        // scan block sums

// -------- degree / CSR build --------
__global__ void k_zero(int n) {
    int i = blockIdx.x * blockDim.x + threadIdx.x;
    if (i < n) { g_cnt[i] = 0; g_cur[i] = 0; }
}

__global__ void k_cnt(const int* __restrict__ col, int E) {
    int i = blockIdx.x * blockDim.x + threadIdx.x;
    if (i < E) atomicAdd(&g_cnt[col[i]], 1);
}

// two-level scan: 512-element blocks
__global__ void __launch_bounds__(512) k_scan1(int n) {
    __shared__ int s[512];
    int t = threadIdx.x;
    int i = blockIdx.x * 512 + t;
    int val = (i < n) ? g_cnt[i] : 0;
    s[t] = val; __syncthreads();
#pragma unroll
    for (int d = 1; d < 512; d <<= 1) {
        int v = (t >= d) ? s[t - d] : 0;
        __syncthreads();
        s[t] += v;
        __syncthreads();
    }
    if (i < n) g_start[i] = s[t] - val;          // exclusive within block
    if (t == 511) g_bsum[blockIdx.x] = s[511];   // block total
}

__global__ void __launch_bounds__(256) k_scan2(int nb) {
    __shared__ int s[256];
    int t = threadIdx.x;
    int val = (t < nb) ? g_bsum[t] : 0;
    s[t] = val; __syncthreads();
#pragma unroll
    for (int d = 1; d < 256; d <<= 1) {
        int v = (t >= d) ? s[t - d] : 0;
        __syncthreads();
        s[t] += v;
        __syncthreads();
    }
    if (t < nb) g_bsum[t] = s[t];                // inclusive
}

__global__ void k_scan3(int n) {
    int i = blockIdx.x * blockDim.x + threadIdx.x;
    if (i >= n) return;
    int b = i >> 9;
    if (b > 0) g_start[i] += g_bsum[b - 1];
    g_dinv[i] = rsqrtf((float)(g_cnt[i] + 1));   // +1 self loop
}

__global__ void k_fill(const int* __restrict__ row, const int* __restrict__ col, int E) {
    int e = blockIdx.x * blockDim.x + threadIdx.x;
    if (e >= E) return;
    int c = col[e];
    int pos = g_start[c] + atomicAdd(&g_cur[c], 1);
    g_adj[pos] = row[e];
}

// ===================== register-tiled LSTM GEMM ============================
// Block: 64 rows x 64 j, 256 threads, each {rg*4..+3, rg*4+32..+3} x 2 j x 3 gates.
__global__ void __launch_bounds__(256) k_lstm(
    const float* __restrict__ x, const float* __restrict__ Wih,
    const float* __restrict__ bih, const float* __restrict__ bhh, int n)
{
    __shared__ float xs[32][68];
    __shared__ float ws[32][192];   // ws[k][g*64+j], gates i,g,o

    const int t  = threadIdx.x;
    const int br = blockIdx.x * 64;
    const int rg = t & 7,  jg = t >> 3;
    const int r0 = rg * 4, j0 = jg * 2;

    float acc[3][2][8];
#pragma unroll
    for (int g = 0; g < 3; g++)
#pragma unroll
        for (int jj = 0; jj < 2; jj++)
#pragma unroll
            for (int r = 0; r < 8; r++) acc[g][jj][r] = 0.f;

#pragma unroll
    for (int kc = 0; kc < 64; kc += 32) {
        if (kc) __syncthreads();
#pragma unroll
        for (int p = 0; p < 2; p++) {
            int l4 = p * 256 + t;
            int kq = l4 & 7, row = l4 >> 3;
            float4 v = make_float4(0.f, 0.f, 0.f, 0.f);
            if (br + row < n)
                v = ((const float4*)x)[(size_t)(br + row) * 16 + (kc >> 2) + kq];
            xs[4 * kq + 0][row] = v.x; xs[4 * kq + 1][row] = v.y;
            xs[4 * kq + 2][row] = v.z; xs[4 * kq + 3][row] = v.w;
        }
#pragma unroll
        for (int p = 0; p < 6; p++) {
            int l4 = p * 256 + t;
            int j  = l4 & 63;
            int gk = l4 >> 6;
            int g  = gk % 3;
            int kq = gk / 3;
            int goff = (g == 0) ? 0 : (g == 1 ? 128 : 192);
            float4 v = ((const float4*)Wih)[(size_t)(goff + j) * 16 + (kc >> 2) + kq];
            ws[4 * kq + 0][g * 64 + j] = v.x; ws[4 * kq + 1][g * 64 + j] = v.y;
            ws[4 * kq + 2][g * 64 + j] = v.z; ws[4 * kq + 3][g * 64 + j] = v.w;
        }
        __syncthreads();

#pragma unroll
        for (int k = 0; k < 32; k++) {
            float4 xa = *(const float4*)&xs[k][r0];        // conflict-free
            float4 xb = *(const float4*)&xs[k][r0 + 32];   // conflict-free
            float2 wi = *(const float2*)&ws[k][j0];
            float2 wg = *(const float2*)&ws[k][64 + j0];
            float2 wo = *(const float2*)&ws[k][128 + j0];
            float xv[8] = {xa.x, xa.y, xa.z, xa.w, xb.x, xb.y, xb.z, xb.w};
            float wv[3][2] = {{wi.x, wi.y}, {wg.x, wg.y}, {wo.x, wo.y}};
#pragma unroll
            for (int g = 0; g < 3; g++)
#pragma unroll
                for (int jj = 0; jj < 2; jj++)
#pragma unroll
                    for (int r = 0; r < 8; r++)
                        acc[g][jj][r] = fmaf(wv[g][jj], xv[r], acc[g][jj][r]);
        }
    }

#pragma unroll
    for (int jj = 0; jj < 2; jj++) {
        int j = j0 + jj;
        float bi = bih[j]       + bhh[j];
        float bg = bih[128 + j] + bhh[128 + j];
        float bo = bih[192 + j] + bhh[192 + j];
#pragma unroll
        for (int r = 0; r < 8; r++) {
            int row = br + r0 + (r < 4 ? r : 28 + r);
            if (row < n) {
                float ai = acc[0][jj][r] + bi;
                float ag = acc[1][jj][r] + bg;
                float ao = acc[2][jj][r] + bo;
                float si = 1.0f / (1.0f + expf(-ai));
                float so = 1.0f / (1.0f + expf(-ao));
                float c  = si * tanhf(ag);
                g_h[(size_t)row * 64 + j] = so * tanhf(c);
            }
        }
    }
}

// ===================== register-tiled GEMM, JOUT=64 ========================
__global__ void __launch_bounds__(128) k_gemm64(
    const float* __restrict__ H, const float* __restrict__ W,
    float* __restrict__ Out, int n)
{
    __shared__ float xs[64][68];
    __shared__ float ws[64][64];

    const int t  = threadIdx.x;
    const int br = blockIdx.x * 64;
    const int rg = t & 7,  jg = t >> 3;
    const int r0 = rg * 4, j0 = jg * 4;

    float acc[4][8];
#pragma unroll
    for (int jj = 0; jj < 4; jj++)
#pragma unroll
        for (int r = 0; r < 8; r++) acc[jj][r] = 0.f;

#pragma unroll
    for (int p = 0; p < 8; p++) {
        int l4 = p * 128 + t;
        int kq = l4 & 15, row = l4 >> 4;
        float4 v = make_float4(0.f, 0.f, 0.f, 0.f);
        if (br + row < n) v = ((const float4*)H)[(size_t)(br + row) * 16 + kq];
        xs[4 * kq + 0][row] = v.x; xs[4 * kq + 1][row] = v.y;
        xs[4 * kq + 2][row] = v.z; xs[4 * kq + 3][row] = v.w;
    }
#pragma unroll
    for (int p = 0; p < 8; p++) {
        int l4 = p * 128 + t;
        ((float4*)ws)[l4] = ((const float4*)W)[l4];
    }
    __syncthreads();

#pragma unroll
    for (int k = 0; k < 64; k++) {
        float4 xa = *(const float4*)&xs[k][r0];
        float4 xb = *(const float4*)&xs[k][r0 + 32];
        float4 w  = *(const float4*)&ws[k][j0];
        float xv[8] = {xa.x, xa.y, xa.z, xa.w, xb.x, xb.y, xb.z, xb.w};
        float wv[4] = {w.x, w.y, w.z, w.w};
#pragma unroll
        for (int jj = 0; jj < 4; jj++)
#pragma unroll
            for (int r = 0; r < 8; r++)
                acc[jj][r] = fmaf(wv[jj], xv[r], acc[jj][r]);
    }

#pragma unroll
    for (int r = 0; r < 8; r++) {
        int row = br + r0 + (r < 4 ? r : 28 + r);
        if (row < n) {
            float4 o = make_float4(acc[0][r], acc[1][r], acc[2][r], acc[3][r]);
            ((float4*)Out)[(size_t)row * 16 + (j0 >> 2)] = o;
        }
    }
}

// ===================== register-tiled GEMM, JOUT=32 ========================
__global__ void __launch_bounds__(256) k_gemm32(
    const float* __restrict__ H, const float* __restrict__ W,
    float* __restrict__ Out, int n)
{
    __shared__ float xs[64][132];
    __shared__ float ws[64][32];

    const int t  = threadIdx.x;
    const int br = blockIdx.x * 128;
    const int rg = t & 15, jg = t >> 4;
    const int r0 = rg * 4, j0 = jg * 2;

    float acc[2][8];
#pragma unroll
    for (int jj = 0; jj < 2; jj++)
#pragma unroll
        for (int r = 0; r < 8; r++) acc[jj][r] = 0.f;

#pragma unroll
    for (int p = 0; p < 8; p++) {
        int l4 = p * 256 + t;
        int kq = l4 & 15, row = l4 >> 4;
        float4 v = make_float4(0.f, 0.f, 0.f, 0.f);
        if (br + row < n) v = ((const float4*)H)[(size_t)(br + row) * 16 + kq];
        xs[4 * kq + 0][row] = v.x; xs[4 * kq + 1][row] = v.y;
        xs[4 * kq + 2][row] = v.z; xs[4 * kq + 3][row] = v.w;
    }
#pragma unroll
    for (int p = 0; p < 2; p++) {
        int l4 = p * 256 + t;
        ((float4*)ws)[l4] = ((const float4*)W)[l4];
    }
    __syncthreads();

#pragma unroll
    for (int k = 0; k < 64; k++) {
        float4 xa = *(const float4*)&xs[k][r0];
        float4 xb = *(const float4*)&xs[k][r0 + 64];
        float2 w  = *(const float2*)&ws[k][j0];
        float xv[8] = {xa.x, xa.y, xa.z, xa.w, xb.x, xb.y, xb.z, xb.w};
        float wv[2] = {w.x, w.y};
#pragma unroll
        for (int jj = 0; jj < 2; jj++)
#pragma unroll
            for (int r = 0; r < 8; r++)
                acc[jj][r] = fmaf(wv[jj], xv[r], acc[jj][r]);
    }

#pragma unroll
    for (int r = 0; r < 8; r++) {
        int row = br + r0 + (r < 4 ? r : 60 + r);
        if (row < n) {
            float2 o = make_float2(acc[0][r], acc[1][r]);
            ((float2*)Out)[(size_t)row * 16 + jg] = o;
        }
    }
}

// ===================== CSR pull GCN aggregation ============================
// V float4-chunks per node feature row; V threads per node.
// out[v] = relu?( dinv[v] * sum_{r in in(v)} dinv[r]*hw[r] + dinv[v]^2*hw[v] + b )
template <int V, bool RELU>
__global__ void __launch_bounds__(256) k_pull(
    const float* __restrict__ HW, const float* __restrict__ bias,
    float* __restrict__ Out, int n)
{
    const int t = threadIdx.x;
    const int v = blockIdx.x * (256 / V) + t / V;
    const int j = t % V;
    if (v >= n) return;

    const int s0 = g_start[v];
    const int s1 = s0 + g_cnt[v];

    float4 acc = make_float4(0.f, 0.f, 0.f, 0.f);
    for (int k = s0; k < s1; k++) {
        int r = g_adj[k];
        float w = g_dinv[r];
        float4 hv = ((const float4*)HW)[(size_t)r * V + j];
        acc.x = fmaf(w, hv.x, acc.x);
        acc.y = fmaf(w, hv.y, acc.y);
        acc.z = fmaf(w, hv.z, acc.z);
        acc.w = fmaf(w, hv.w, acc.w);
    }

    float dv = g_dinv[v];
    float sl = dv * dv;
    float4 hv = ((const float4*)HW)[(size_t)v * V + j];
    float4 b  = ((const float4*)bias)[j];
    float4 o;
    o.x = fmaf(dv, acc.x, fmaf(sl, hv.x, b.x));
    o.y = fmaf(dv, acc.y, fmaf(sl, hv.y, b.y));
    o.z = fmaf(dv, acc.z, fmaf(sl, hv.z, b.z));
    o.w = fmaf(dv, acc.w, fmaf(sl, hv.w, b.w));
    if (RELU) {
        o.x = fmaxf(o.x, 0.f); o.y = fmaxf(o.y, 0.f);
        o.z = fmaxf(o.z, 0.f); o.w = fmaxf(o.w, 0.f);
    }
    ((float4*)Out)[(size_t)v * V + j] = o;
}

// -------- edge dot --------
__global__ void k_edot(const int* __restrict__ eli, float* __restrict__ out, int EL)
{
    int gid = blockIdx.x * blockDim.x + threadIdx.x;
    if (gid >= EL * 8) return;
    int e = gid >> 3;
    int j = gid & 7;
    int s = eli[e];
    int d = eli[EL + e];
    float4 a = ((const float4*)g_z)[(size_t)s * 8 + j];
    float4 b = ((const float4*)g_z)[(size_t)d * 8 + j];
    float p = a.x * b.x + a.y * b.y + a.z * b.z + a.w * b.w;
    p += __shfl_down_sync(0xffffffffu, p, 4);
    p += __shfl_down_sync(0xffffffffu, p, 2);
    p += __shfl_down_sync(0xffffffffu, p, 1);
    if (j == 0) out[e] = p;
}

extern "C" void kernel_launch(void* const* d_in, const int* in_sizes, int n_in,
                              void* d_out, int out_size)
{
    (void)n_in; (void)out_size;
    const float* x   = (const float*)d_in[0];
    const int*   ei  = (const int*)  d_in[1];
    const int*   eli = (const int*)  d_in[2];
    const float* Wih = (const float*)d_in[3];
    const float* bih = (const float*)d_in[5];
    const float* bhh = (const float*)d_in[6];
    const float* W1  = (const float*)d_in[7];
    const float* b1  = (const float*)d_in[8];
    const float* W2  = (const float*)d_in[9];
    const float* b2  = (const float*)d_in[10];
    float* out = (float*)d_out;

    int n  = in_sizes[0] / 64;
    int E  = in_sizes[1] / 2;
    int EL = in_sizes[2] / 2;
    const int* row = ei;
    const int* col = ei + E;

    float *p_h, *p_hw1, *p_hw2, *p_z;
    cudaGetSymbolAddress((void**)&p_h,   g_h);
    cudaGetSymbolAddress((void**)&p_hw1, g_hw1);
    cudaGetSymbolAddress((void**)&p_hw2, g_hw2);
    cudaGetSymbolAddress((void**)&p_z,   g_z);

    const int T = 256;
    int nb = (n + 511) / 512;

    // CSR build
    k_zero <<<(n + T - 1) / T, T>>>(n);
    k_cnt  <<<(E + T - 1) / T, T>>>(col, E);
    k_scan1<<<nb, 512>>>(n);
    k_scan2<<<1, 256>>>(nb);
    k_scan3<<<(n + T - 1) / T, T>>>(n);
    k_fill <<<(E + T - 1) / T, T>>>(row, col, E);

    // network
    k_lstm  <<<(n + 63) / 64, 256>>>(x, Wih, bih, bhh, n);
    k_gemm64<<<(n + 63) / 64, 128>>>(p_h, W1, p_hw1, n);
    k_pull<16, true><<<(n * 16 + T - 1) / T, T>>>(p_hw1, b1, p_h, n);
    k_gemm32<<<(n + 127) / 128, 256>>>(p_h, W2, p_hw2, n);
    k_pull<8, false><<<(n * 8 + T - 1) / T, T>>>(p_hw2, b2, p_z, n);
    k_edot<<<(EL * 8 + T - 1) / T, T>>>(eli, out, EL);
}

// round 4
// speedup vs baseline: 1.7927x; 1.0820x over previous
#include <cuda_runtime.h>
#include <math.h>

#define MAXN 100000
#define MAXE 1600000

// -------- scratch (device globals; no allocations allowed) --------
__device__ float g_h   [MAXN * 64];
__device__ float g_hw1 [MAXN * 64];
__device__ float g_hw2 [MAXN * 32];
__device__ float g_z   [MAXN * 32];
__device__ float g_dinv[MAXN];
__device__ int   g_cnt [MAXN];
__device__ int   g_start[MAXN];
__device__ int   g_cur [MAXN];
__device__ int   g_adj [MAXE];
__device__ int   g_bsum[256];

// -------- packed f32x2 helpers (Blackwell) --------
#define PACK2(d, lo, hi) \
    asm("mov.b64 %0, {%1, %2};" : "=l"(d) : "f"(lo), "f"(hi))
#define UNPACK2(lo, hi, s) \
    asm("mov.b64 {%0, %1}, %2;" : "=f"(lo), "=f"(hi) : "l"(s))
#define FMA2(acc, a, b) \
    asm("fma.rn.f32x2 %0, %1, %2, %0;" : "+l"(acc) : "l"(a), "l"(b))

__device__ __forceinline__ float fast_sigmoid(float a) {
    return __fdividef(1.0f, 1.0f + __expf(-a));
}
__device__ __forceinline__ float fast_tanh(float a) {
    // 1 - 2/(e^{2a}+1); saturates correctly at +-inf
    return 1.0f - __fdividef(2.0f, __expf(2.0f * a) + 1.0f);
}

// -------- degree / CSR build --------
__global__ void k_zero(int n) {
    int i = blockIdx.x * blockDim.x + threadIdx.x;
    if (i < n) { g_cnt[i] = 0; g_cur[i] = 0; }
}

__global__ void k_cnt(const int* __restrict__ col, int E) {
    int i = blockIdx.x * blockDim.x + threadIdx.x;
    if (i < E) atomicAdd(&g_cnt[col[i]], 1);
}

__global__ void __launch_bounds__(512) k_scan1(int n) {
    __shared__ int s[512];
    int t = threadIdx.x;
    int i = blockIdx.x * 512 + t;
    int val = (i < n) ? g_cnt[i] : 0;
    s[t] = val; __syncthreads();
#pragma unroll
    for (int d = 1; d < 512; d <<= 1) {
        int v = (t >= d) ? s[t - d] : 0;
        __syncthreads();
        s[t] += v;
        __syncthreads();
    }
    if (i < n) g_start[i] = s[t] - val;
    if (t == 511) g_bsum[blockIdx.x] = s[511];
}

__global__ void __launch_bounds__(256) k_scan2(int nb) {
    __shared__ int s[256];
    int t = threadIdx.x;
    int val = (t < nb) ? g_bsum[t] : 0;
    s[t] = val; __syncthreads();
#pragma unroll
    for (int d = 1; d < 256; d <<= 1) {
        int v = (t >= d) ? s[t - d] : 0;
        __syncthreads();
        s[t] += v;
        __syncthreads();
    }
    if (t < nb) g_bsum[t] = s[t];
}

__global__ void k_scan3(int n) {
    int i = blockIdx.x * blockDim.x + threadIdx.x;
    if (i >= n) return;
    int b = i >> 9;
    if (b > 0) g_start[i] += g_bsum[b - 1];
    g_dinv[i] = rsqrtf((float)(g_cnt[i] + 1));
}

__global__ void k_fill(const int* __restrict__ row, const int* __restrict__ col, int E) {
    int e = blockIdx.x * blockDim.x + threadIdx.x;
    if (e >= E) return;
    int c = col[e];
    int pos = g_start[c] + atomicAdd(&g_cur[c], 1);
    g_adj[pos] = row[e];
}

// ===================== register-tiled LSTM GEMM (f32x2) ====================
// Block: 64 rows x 64 j, 256 threads. Per thread: row-pairs
// {r0,r0+1},{r0+2,r0+3},{r0+32,r0+33},{r0+34,r0+35} x 2 j x 3 gates.
__global__ void __launch_bounds__(256) k_lstm(
    const float* __restrict__ x, const float* __restrict__ Wih,
    const float* __restrict__ bih, const float* __restrict__ bhh, int n)
{
    __shared__ float xs[32][68];
    __shared__ float ws[32][192];   // ws[k][g*64+j], gates i,g,o

    const int t  = threadIdx.x;
    const int br = blockIdx.x * 64;
    const int rg = t & 7,  jg = t >> 3;
    const int r0 = rg * 4, j0 = jg * 2;

    unsigned long long acc[3][2][4];
#pragma unroll
    for (int g = 0; g < 3; g++)
#pragma unroll
        for (int jj = 0; jj < 2; jj++)
#pragma unroll
            for (int p = 0; p < 4; p++) acc[g][jj][p] = 0ull;

#pragma unroll
    for (int kc = 0; kc < 64; kc += 32) {
        if (kc) __syncthreads();
#pragma unroll
        for (int p = 0; p < 2; p++) {
            int l4 = p * 256 + t;
            int kq = l4 & 7, row = l4 >> 3;
            float4 v = make_float4(0.f, 0.f, 0.f, 0.f);
            if (br + row < n)
                v = ((const float4*)x)[(size_t)(br + row) * 16 + (kc >> 2) + kq];
            xs[4 * kq + 0][row] = v.x; xs[4 * kq + 1][row] = v.y;
            xs[4 * kq + 2][row] = v.z; xs[4 * kq + 3][row] = v.w;
        }
#pragma unroll
        for (int p = 0; p < 6; p++) {
            int l4 = p * 256 + t;
            int j  = l4 & 63;
            int gk = l4 >> 6;
            int g  = gk % 3;
            int kq = gk / 3;
            int goff = (g == 0) ? 0 : (g == 1 ? 128 : 192);
            float4 v = ((const float4*)Wih)[(size_t)(goff + j) * 16 + (kc >> 2) + kq];
            ws[4 * kq + 0][g * 64 + j] = v.x; ws[4 * kq + 1][g * 64 + j] = v.y;
            ws[4 * kq + 2][g * 64 + j] = v.z; ws[4 * kq + 3][g * 64 + j] = v.w;
        }
        __syncthreads();

#pragma unroll
        for (int k = 0; k < 32; k++) {
            float4 xa = *(const float4*)&xs[k][r0];
            float4 xb = *(const float4*)&xs[k][r0 + 32];
            float2 wi = *(const float2*)&ws[k][j0];
            float2 wg = *(const float2*)&ws[k][64 + j0];
            float2 wo = *(const float2*)&ws[k][128 + j0];

            unsigned long long xp[4];
            PACK2(xp[0], xa.x, xa.y); PACK2(xp[1], xa.z, xa.w);
            PACK2(xp[2], xb.x, xb.y); PACK2(xp[3], xb.z, xb.w);

            unsigned long long wp[3][2];
            PACK2(wp[0][0], wi.x, wi.x); PACK2(wp[0][1], wi.y, wi.y);
            PACK2(wp[1][0], wg.x, wg.x); PACK2(wp[1][1], wg.y, wg.y);
            PACK2(wp[2][0], wo.x, wo.x); PACK2(wp[2][1], wo.y, wo.y);

#pragma unroll
            for (int g = 0; g < 3; g++)
#pragma unroll
                for (int jj = 0; jj < 2; jj++)
#pragma unroll
                    for (int p = 0; p < 4; p++)
                        FMA2(acc[g][jj][p], xp[p], wp[g][jj]);
        }
    }

#pragma unroll
    for (int jj = 0; jj < 2; jj++) {
        int j = j0 + jj;
        float bi = bih[j]       + bhh[j];
        float bg = bih[128 + j] + bhh[128 + j];
        float bo = bih[192 + j] + bhh[192 + j];
#pragma unroll
        for (int p = 0; p < 4; p++) {
            int rowlo = br + r0 + (p < 2 ? 2 * p : 28 + 2 * p);  // p=0:+0 p=1:+2 p=2:+32 p=3:+34
            float ilo, ihi, glo, ghi, olo, ohi;
            UNPACK2(ilo, ihi, acc[0][jj][p]);
            UNPACK2(glo, ghi, acc[1][jj][p]);
            UNPACK2(olo, ohi, acc[2][jj][p]);
#pragma unroll
            for (int h = 0; h < 2; h++) {
                int row = rowlo + h;
                if (row < n) {
                    float ai = (h ? ihi : ilo) + bi;
                    float ag = (h ? ghi : glo) + bg;
                    float ao = (h ? ohi : olo) + bo;
                    float c  = fast_sigmoid(ai) * fast_tanh(ag);
                    g_h[(size_t)row * 64 + j] = fast_sigmoid(ao) * fast_tanh(c);
                }
            }
        }
    }
}

// ===================== register-tiled GEMM, JOUT=64 (f32x2) ================
__global__ void __launch_bounds__(128) k_gemm64(
    const float* __restrict__ H, const float* __restrict__ W,
    float* __restrict__ Out, int n)
{
    __shared__ float xs[64][68];
    __shared__ float ws[64][64];

    const int t  = threadIdx.x;
    const int br = blockIdx.x * 64;
    const int rg = t & 7,  jg = t >> 3;
    const int r0 = rg * 4, j0 = jg * 4;

    unsigned long long acc[4][4];   // [j][rowpair]
#pragma unroll
    for (int jj = 0; jj < 4; jj++)
#pragma unroll
        for (int p = 0; p < 4; p++) acc[jj][p] = 0ull;

#pragma unroll
    for (int p = 0; p < 8; p++) {
        int l4 = p * 128 + t;
        int kq = l4 & 15, row = l4 >> 4;
        float4 v = make_float4(0.f, 0.f, 0.f, 0.f);
        if (br + row < n) v = ((const float4*)H)[(size_t)(br + row) * 16 + kq];
        xs[4 * kq + 0][row] = v.x; xs[4 * kq + 1][row] = v.y;
        xs[4 * kq + 2][row] = v.z; xs[4 * kq + 3][row] = v.w;
    }
#pragma unroll
    for (int p = 0; p < 8; p++) {
        int l4 = p * 128 + t;
        ((float4*)ws)[l4] = ((const float4*)W)[l4];
    }
    __syncthreads();

#pragma unroll
    for (int k = 0; k < 64; k++) {
        float4 xa = *(const float4*)&xs[k][r0];
        float4 xb = *(const float4*)&xs[k][r0 + 32];
        float4 w  = *(const float4*)&ws[k][j0];

        unsigned long long xp[4];
        PACK2(xp[0], xa.x, xa.y); PACK2(xp[1], xa.z, xa.w);
        PACK2(xp[2], xb.x, xb.y); PACK2(xp[3], xb.z, xb.w);
        unsigned long long wp[4];
        PACK2(wp[0], w.x, w.x); PACK2(wp[1], w.y, w.y);
        PACK2(wp[2], w.z, w.z); PACK2(wp[3], w.w, w.w);

#pragma unroll
        for (int jj = 0; jj < 4; jj++)
#pragma unroll
            for (int p = 0; p < 4; p++)
                FMA2(acc[jj][p], xp[p], wp[jj]);
    }

#pragma unroll
    for (int p = 0; p < 4; p++) {
        int rowlo = br + r0 + (p < 2 ? 2 * p : 28 + 2 * p);
        float lo[4], hi[4];
#pragma unroll
        for (int jj = 0; jj < 4; jj++) UNPACK2(lo[jj], hi[jj], acc[jj][p]);
        if (rowlo < n)
            ((float4*)Out)[(size_t)rowlo * 16 + (j0 >> 2)] =
                make_float4(lo[0], lo[1], lo[2], lo[3]);
        if (rowlo + 1 < n)
            ((float4*)Out)[(size_t)(rowlo + 1) * 16 + (j0 >> 2)] =
                make_float4(hi[0], hi[1], hi[2], hi[3]);
    }
}

// ===================== register-tiled GEMM, JOUT=32 (f32x2) ================
__global__ void __launch_bounds__(256) k_gemm32(
    const float* __restrict__ H, const float* __restrict__ W,
    float* __restrict__ Out, int n)
{
    __shared__ float xs[64][132];
    __shared__ float ws[64][32];

    const int t  = threadIdx.x;
    const int br = blockIdx.x * 128;
    const int rg = t & 15, jg = t >> 4;
    const int r0 = rg * 4, j0 = jg * 2;

    unsigned long long acc[2][4];
#pragma unroll
    for (int jj = 0; jj < 2; jj++)
#pragma unroll
        for (int p = 0; p < 4; p++) acc[jj][p] = 0ull;

#pragma unroll
    for (int p = 0; p < 8; p++) {
        int l4 = p * 256 + t;
        int kq = l4 & 15, row = l4 >> 4;
        float4 v = make_float4(0.f, 0.f, 0.f, 0.f);
        if (br + row < n) v = ((const float4*)H)[(size_t)(br + row) * 16 + kq];
        xs[4 * kq + 0][row] = v.x; xs[4 * kq + 1][row] = v.y;
        xs[4 * kq + 2][row] = v.z; xs[4 * kq + 3][row] = v.w;
    }
#pragma unroll
    for (int p = 0; p < 2; p++) {
        int l4 = p * 256 + t;
        ((float4*)ws)[l4] = ((const float4*)W)[l4];
    }
    __syncthreads();

#pragma unroll
    for (int k = 0; k < 64; k++) {
        float4 xa = *(const float4*)&xs[k][r0];
        float4 xb = *(const float4*)&xs[k][r0 + 64];
        float2 w  = *(const float2*)&ws[k][j0];

        unsigned long long xp[4];
        PACK2(xp[0], xa.x, xa.y); PACK2(xp[1], xa.z, xa.w);
        PACK2(xp[2], xb.x, xb.y); PACK2(xp[3], xb.z, xb.w);
        unsigned long long wp[2];
        PACK2(wp[0], w.x, w.x); PACK2(wp[1], w.y, w.y);

#pragma unroll
        for (int jj = 0; jj < 2; jj++)
#pragma unroll
            for (int p = 0; p < 4; p++)
                FMA2(acc[jj][p], xp[p], wp[jj]);
    }

#pragma unroll
    for (int p = 0; p < 4; p++) {
        int rowlo = br + r0 + (p < 2 ? 2 * p : 60 + 2 * p);  // p=2:+64 p=3:+66
        float lo0, hi0, lo1, hi1;
        UNPACK2(lo0, hi0, acc[0][p]);
        UNPACK2(lo1, hi1, acc[1][p]);
        if (rowlo < n)
            ((float2*)Out)[(size_t)rowlo * 16 + jg] = make_float2(lo0, lo1);
        if (rowlo + 1 < n)
            ((float2*)Out)[(size_t)(rowlo + 1) * 16 + jg] = make_float2(hi0, hi1);
    }
}

// ===================== CSR pull GCN aggregation ============================
template <int V, bool RELU>
__global__ void __launch_bounds__(256) k_pull(
    const float* __restrict__ HW, const float* __restrict__ bias,
    float* __restrict__ Out, int n)
{
    const int t = threadIdx.x;
    const int v = blockIdx.x * (256 / V) + t / V;
    const int j = t % V;
    if (v >= n) return;

    const int s0 = g_start[v];
    const int s1 = s0 + g_cnt[v];

    float4 acc = make_float4(0.f, 0.f, 0.f, 0.f);
    for (int k = s0; k < s1; k++) {
        int r = g_adj[k];
        float w = g_dinv[r];
        float4 hv = ((const float4*)HW)[(size_t)r * V + j];
        acc.x = fmaf(w, hv.x, acc.x);
        acc.y = fmaf(w, hv.y, acc.y);
        acc.z = fmaf(w, hv.z, acc.z);
        acc.w = fmaf(w, hv.w, acc.w);
    }

    float dv = g_dinv[v];
    float sl = dv * dv;
    float4 hv = ((const float4*)HW)[(size_t)v * V + j];
    float4 b  = ((const float4*)bias)[j];
    float4 o;
    o.x = fmaf(dv, acc.x, fmaf(sl, hv.x, b.x));
    o.y = fmaf(dv, acc.y, fmaf(sl, hv.y, b.y));
    o.z = fmaf(dv, acc.z, fmaf(sl, hv.z, b.z));
    o.w = fmaf(dv, acc.w, fmaf(sl, hv.w, b.w));
    if (RELU) {
        o.x = fmaxf(o.x, 0.f); o.y = fmaxf(o.y, 0.f);
        o.z = fmaxf(o.z, 0.f); o.w = fmaxf(o.w, 0.f);
    }
    ((float4*)Out)[(size_t)v * V + j] = o;
}

// -------- edge dot --------
__global__ void k_edot(const int* __restrict__ eli, float* __restrict__ out, int EL)
{
    int gid = blockIdx.x * blockDim.x + threadIdx.x;
    if (gid >= EL * 8) return;
    int e = gid >> 3;
    int j = gid & 7;
    int s = eli[e];
    int d = eli[EL + e];
    float4 a = ((const float4*)g_z)[(size_t)s * 8 + j];
    float4 b = ((const float4*)g_z)[(size_t)d * 8 + j];
    float p = a.x * b.x + a.y * b.y + a.z * b.z + a.w * b.w;
    p += __shfl_down_sync(0xffffffffu, p, 4);
    p += __shfl_down_sync(0xffffffffu, p, 2);
    p += __shfl_down_sync(0xffffffffu, p, 1);
    if (j == 0) out[e] = p;
}

extern "C" void kernel_launch(void* const* d_in, const int* in_sizes, int n_in,
                              void* d_out, int out_size)
{
    (void)n_in; (void)out_size;
    const float* x   = (const float*)d_in[0];
    const int*   ei  = (const int*)  d_in[1];
    const int*   eli = (const int*)  d_in[2];
    const float* Wih = (const float*)d_in[3];
    const float* bih = (const float*)d_in[5];
    const float* bhh = (const float*)d_in[6];
    const float* W1  = (const float*)d_in[7];
    const float* b1  = (const float*)d_in[8];
    const float* W2  = (const float*)d_in[9];
    const float* b2  = (const float*)d_in[10];
    float* out = (float*)d_out;

    int n  = in_sizes[0] / 64;
    int E  = in_sizes[1] / 2;
    int EL = in_sizes[2] / 2;
    const int* row = ei;
    const int* col = ei + E;

    float *p_h, *p_hw1, *p_hw2, *p_z;
    cudaGetSymbolAddress((void**)&p_h,   g_h);
    cudaGetSymbolAddress((void**)&p_hw1, g_hw1);
    cudaGetSymbolAddress((void**)&p_hw2, g_hw2);
    cudaGetSymbolAddress((void**)&p_z,   g_z);

    const int T = 256;
    int nb = (n + 511) / 512;

    // CSR build
    k_zero <<<(n + T - 1) / T, T>>>(n);
    k_cnt  <<<(E + T - 1) / T, T>>>(col, E);
    k_scan1<<<nb, 512>>>(n);
    k_scan2<<<1, 256>>>(nb);
    k_scan3<<<(n + T - 1) / T, T>>>(n);
    k_fill <<<(E + T - 1) / T, T>>>(row, col, E);

    // network
    k_lstm  <<<(n + 63) / 64, 256>>>(x, Wih, bih, bhh, n);
    k_gemm64<<<(n + 63) / 64, 128>>>(p_h, W1, p_hw1, n);
    k_pull<16, true><<<(n * 16 + T - 1) / T, T>>>(p_hw1, b1, p_h, n);
    k_gemm32<<<(n + 127) / 128, 256>>>(p_h, W2, p_hw2, n);
    k_pull<8, false><<<(n * 8 + T - 1) / T, T>>>(p_hw2, b2, p_z, n);
    k_edot<<<(EL * 8 + T - 1) / T, T>>>(eli, out, EL);
}

// round 5
// speedup vs baseline: 2.0583x; 1.1482x over previous
#include <cuda_runtime.h>
#include <cuda_fp16.h>
#include <math.h>

#define MAXN 100000
#define MAXE 1600000

// -------- scratch (device globals; no allocations allowed) --------
__device__ float   g_h   [MAXN * 64];   // LSTM out; later relu(conv1) out (fp32: GEMM input)
__device__ __half2 g_hw1h[MAXN * 32];   // h  @ W1  (fp16 rows: gather-side)
__device__ __half2 g_hw2h[MAXN * 16];   // h2 @ W2
__device__ __half2 g_zh  [MAXN * 16];   // conv2 out z (fp16: edot gathers)
__device__ float   g_dinv[MAXN];
__device__ int     g_cnt [MAXN];
__device__ int     g_start[MAXN];
__device__ int     g_cur [MAXN];
__device__ int     g_adj [MAXE];
__device__ int     g_bsum[256];

// -------- packed f32x2 helpers (Blackwell) --------
#define PACK2(d, lo, hi) \
    asm("mov.b64 %0, {%1, %2};" : "=l"(d) : "f"(lo), "f"(hi))
#define UNPACK2(lo, hi, s) \
    asm("mov.b64 {%0, %1}, %2;" : "=f"(lo), "=f"(hi) : "l"(s))
#define FMA2(acc, a, b) \
    asm("fma.rn.f32x2 %0, %1, %2, %0;" : "+l"(acc) : "l"(a), "l"(b))

__device__ __forceinline__ float fast_sigmoid(float a) {
    return __fdividef(1.0f, 1.0f + __expf(-a));
}
__device__ __forceinline__ float fast_tanh(float a) {
    return 1.0f - __fdividef(2.0f, __expf(2.0f * a) + 1.0f);
}

// -------- degree / CSR build --------
__global__ void k_zero(int n) {
    int i = blockIdx.x * blockDim.x + threadIdx.x;
    if (i < n) { g_cnt[i] = 0; g_cur[i] = 0; }
}

__global__ void k_cnt(const int* __restrict__ col, int E) {
    int i = blockIdx.x * blockDim.x + threadIdx.x;
    if (i < E) atomicAdd(&g_cnt[col[i]], 1);
}

__global__ void __launch_bounds__(512) k_scan1(int n) {
    __shared__ int s[512];
    int t = threadIdx.x;
    int i = blockIdx.x * 512 + t;
    int val = (i < n) ? g_cnt[i] : 0;
    s[t] = val; __syncthreads();
#pragma unroll
    for (int d = 1; d < 512; d <<= 1) {
        int v = (t >= d) ? s[t - d] : 0;
        __syncthreads();
        s[t] += v;
        __syncthreads();
    }
    if (i < n) g_start[i] = s[t] - val;
    if (t == 511) g_bsum[blockIdx.x] = s[511];
}

__global__ void __launch_bounds__(256) k_scan2(int nb) {
    __shared__ int s[256];
    int t = threadIdx.x;
    int val = (t < nb) ? g_bsum[t] : 0;
    s[t] = val; __syncthreads();
#pragma unroll
    for (int d = 1; d < 256; d <<= 1) {
        int v = (t >= d) ? s[t - d] : 0;
        __syncthreads();
        s[t] += v;
        __syncthreads();
    }
    if (t < nb) g_bsum[t] = s[t];
}

__global__ void k_scan3(int n) {
    int i = blockIdx.x * blockDim.x + threadIdx.x;
    if (i >= n) return;
    int b = i >> 9;
    if (b > 0) g_start[i] += g_bsum[b - 1];
    g_dinv[i] = rsqrtf((float)(g_cnt[i] + 1));
}

__global__ void k_fill(const int* __restrict__ row, const int* __restrict__ col, int E) {
    int e = blockIdx.x * blockDim.x + threadIdx.x;
    if (e >= E) return;
    int c = col[e];
    int pos = g_start[c] + atomicAdd(&g_cur[c], 1);
    g_adj[pos] = row[e];
}

// ===================== register-tiled LSTM GEMM (f32x2) ====================
__global__ void __launch_bounds__(256) k_lstm(
    const float* __restrict__ x, const float* __restrict__ Wih,
    const float* __restrict__ bih, const float* __restrict__ bhh, int n)
{
    __shared__ float xs[32][68];
    __shared__ float ws[32][192];

    const int t  = threadIdx.x;
    const int br = blockIdx.x * 64;
    const int rg = t & 7,  jg = t >> 3;
    const int r0 = rg * 4, j0 = jg * 2;

    unsigned long long acc[3][2][4];
#pragma unroll
    for (int g = 0; g < 3; g++)
#pragma unroll
        for (int jj = 0; jj < 2; jj++)
#pragma unroll
            for (int p = 0; p < 4; p++) acc[g][jj][p] = 0ull;

#pragma unroll
    for (int kc = 0; kc < 64; kc += 32) {
        if (kc) __syncthreads();
#pragma unroll
        for (int p = 0; p < 2; p++) {
            int l4 = p * 256 + t;
            int kq = l4 & 7, row = l4 >> 3;
            float4 v = make_float4(0.f, 0.f, 0.f, 0.f);
            if (br + row < n)
                v = ((const float4*)x)[(size_t)(br + row) * 16 + (kc >> 2) + kq];
            xs[4 * kq + 0][row] = v.x; xs[4 * kq + 1][row] = v.y;
            xs[4 * kq + 2][row] = v.z; xs[4 * kq + 3][row] = v.w;
        }
#pragma unroll
        for (int p = 0; p < 6; p++) {
            int l4 = p * 256 + t;
            int j  = l4 & 63;
            int gk = l4 >> 6;
            int g  = gk % 3;
            int kq = gk / 3;
            int goff = (g == 0) ? 0 : (g == 1 ? 128 : 192);
            float4 v = ((const float4*)Wih)[(size_t)(goff + j) * 16 + (kc >> 2) + kq];
            ws[4 * kq + 0][g * 64 + j] = v.x; ws[4 * kq + 1][g * 64 + j] = v.y;
            ws[4 * kq + 2][g * 64 + j] = v.z; ws[4 * kq + 3][g * 64 + j] = v.w;
        }
        __syncthreads();

#pragma unroll
        for (int k = 0; k < 32; k++) {
            float4 xa = *(const float4*)&xs[k][r0];
            float4 xb = *(const float4*)&xs[k][r0 + 32];
            float2 wi = *(const float2*)&ws[k][j0];
            float2 wg = *(const float2*)&ws[k][64 + j0];
            float2 wo = *(const float2*)&ws[k][128 + j0];

            unsigned long long xp[4];
            PACK2(xp[0], xa.x, xa.y); PACK2(xp[1], xa.z, xa.w);
            PACK2(xp[2], xb.x, xb.y); PACK2(xp[3], xb.z, xb.w);

            unsigned long long wp[3][2];
            PACK2(wp[0][0], wi.x, wi.x); PACK2(wp[0][1], wi.y, wi.y);
            PACK2(wp[1][0], wg.x, wg.x); PACK2(wp[1][1], wg.y, wg.y);
            PACK2(wp[2][0], wo.x, wo.x); PACK2(wp[2][1], wo.y, wo.y);

#pragma unroll
            for (int g = 0; g < 3; g++)
#pragma unroll
                for (int jj = 0; jj < 2; jj++)
#pragma unroll
                    for (int p = 0; p < 4; p++)
                        FMA2(acc[g][jj][p], xp[p], wp[g][jj]);
        }
    }

#pragma unroll
    for (int jj = 0; jj < 2; jj++) {
        int j = j0 + jj;
        float bi = bih[j]       + bhh[j];
        float bg = bih[128 + j] + bhh[128 + j];
        float bo = bih[192 + j] + bhh[192 + j];
#pragma unroll
        for (int p = 0; p < 4; p++) {
            int rowlo = br + r0 + (p < 2 ? 2 * p : 28 + 2 * p);
            float ilo, ihi, glo, ghi, olo, ohi;
            UNPACK2(ilo, ihi, acc[0][jj][p]);
            UNPACK2(glo, ghi, acc[1][jj][p]);
            UNPACK2(olo, ohi, acc[2][jj][p]);
#pragma unroll
            for (int h = 0; h < 2; h++) {
                int row = rowlo + h;
                if (row < n) {
                    float ai = (h ? ihi : ilo) + bi;
                    float ag = (h ? ghi : glo) + bg;
                    float ao = (h ? ohi : olo) + bo;
                    float c  = fast_sigmoid(ai) * fast_tanh(ag);
                    g_h[(size_t)row * 64 + j] = fast_sigmoid(ao) * fast_tanh(c);
                }
            }
        }
    }
}

// ===================== GEMM JOUT=64 (f32x2) -> fp16 rows ===================
__global__ void __launch_bounds__(128) k_gemm64(
    const float* __restrict__ H, const float* __restrict__ W,
    __half2* __restrict__ Out, int n)
{
    __shared__ float xs[64][68];
    __shared__ float ws[64][64];

    const int t  = threadIdx.x;
    const int br = blockIdx.x * 64;
    const int rg = t & 7,  jg = t >> 3;
    const int r0 = rg * 4, j0 = jg * 4;

    unsigned long long acc[4][4];
#pragma unroll
    for (int jj = 0; jj < 4; jj++)
#pragma unroll
        for (int p = 0; p < 4; p++) acc[jj][p] = 0ull;

#pragma unroll
    for (int p = 0; p < 8; p++) {
        int l4 = p * 128 + t;
        int kq = l4 & 15, row = l4 >> 4;
        float4 v = make_float4(0.f, 0.f, 0.f, 0.f);
        if (br + row < n) v = ((const float4*)H)[(size_t)(br + row) * 16 + kq];
        xs[4 * kq + 0][row] = v.x; xs[4 * kq + 1][row] = v.y;
        xs[4 * kq + 2][row] = v.z; xs[4 * kq + 3][row] = v.w;
    }
#pragma unroll
    for (int p = 0; p < 8; p++) {
        int l4 = p * 128 + t;
        ((float4*)ws)[l4] = ((const float4*)W)[l4];
    }
    __syncthreads();

#pragma unroll
    for (int k = 0; k < 64; k++) {
        float4 xa = *(const float4*)&xs[k][r0];
        float4 xb = *(const float4*)&xs[k][r0 + 32];
        float4 w  = *(const float4*)&ws[k][j0];

        unsigned long long xp[4];
        PACK2(xp[0], xa.x, xa.y); PACK2(xp[1], xa.z, xa.w);
        PACK2(xp[2], xb.x, xb.y); PACK2(xp[3], xb.z, xb.w);
        unsigned long long wp[4];
        PACK2(wp[0], w.x, w.x); PACK2(wp[1], w.y, w.y);
        PACK2(wp[2], w.z, w.z); PACK2(wp[3], w.w, w.w);

#pragma unroll
        for (int jj = 0; jj < 4; jj++)
#pragma unroll
            for (int p = 0; p < 4; p++)
                FMA2(acc[jj][p], xp[p], wp[jj]);
    }

#pragma unroll
    for (int p = 0; p < 4; p++) {
        int rowlo = br + r0 + (p < 2 ? 2 * p : 28 + 2 * p);
        float lo[4], hi[4];
#pragma unroll
        for (int jj = 0; jj < 4; jj++) UNPACK2(lo[jj], hi[jj], acc[jj][p]);
        if (rowlo < n) {
            uint2 u;
            *(__half2*)&u.x = __floats2half2_rn(lo[0], lo[1]);
            *(__half2*)&u.y = __floats2half2_rn(lo[2], lo[3]);
            ((uint2*)Out)[(size_t)rowlo * 16 + (j0 >> 2)] = u;
        }
        if (rowlo + 1 < n) {
            uint2 u;
            *(__half2*)&u.x = __floats2half2_rn(hi[0], hi[1]);
            *(__half2*)&u.y = __floats2half2_rn(hi[2], hi[3]);
            ((uint2*)Out)[(size_t)(rowlo + 1) * 16 + (j0 >> 2)] = u;
        }
    }
}

// ===================== GEMM JOUT=32 (f32x2) -> fp16 rows ===================
__global__ void __launch_bounds__(256) k_gemm32(
    const float* __restrict__ H, const float* __restrict__ W,
    __half2* __restrict__ Out, int n)
{
    __shared__ float xs[64][132];
    __shared__ float ws[64][32];

    const int t  = threadIdx.x;
    const int br = blockIdx.x * 128;
    const int rg = t & 15, jg = t >> 4;
    const int r0 = rg * 4, j0 = jg * 2;

    unsigned long long acc[2][4];
#pragma unroll
    for (int jj = 0; jj < 2; jj++)
#pragma unroll
        for (int p = 0; p < 4; p++) acc[jj][p] = 0ull;

#pragma unroll
    for (int p = 0; p < 8; p++) {
        int l4 = p * 256 + t;
        int kq = l4 & 15, row = l4 >> 4;
        float4 v = make_float4(0.f, 0.f, 0.f, 0.f);
        if (br + row < n) v = ((const float4*)H)[(size_t)(br + row) * 16 + kq];
        xs[4 * kq + 0][row] = v.x; xs[4 * kq + 1][row] = v.y;
        xs[4 * kq + 2][row] = v.z; xs[4 * kq + 3][row] = v.w;
    }
#pragma unroll
    for (int p = 0; p < 2; p++) {
        int l4 = p * 256 + t;
        ((float4*)ws)[l4] = ((const float4*)W)[l4];
    }
    __syncthreads();

#pragma unroll
    for (int k = 0; k < 64; k++) {
        float4 xa = *(const float4*)&xs[k][r0];
        float4 xb = *(const float4*)&xs[k][r0 + 64];
        float2 w  = *(const float2*)&ws[k][j0];

        unsigned long long xp[4];
        PACK2(xp[0], xa.x, xa.y); PACK2(xp[1], xa.z, xa.w);
        PACK2(xp[2], xb.x, xb.y); PACK2(xp[3], xb.z, xb.w);
        unsigned long long wp[2];
        PACK2(wp[0], w.x, w.x); PACK2(wp[1], w.y, w.y);

#pragma unroll
        for (int jj = 0; jj < 2; jj++)
#pragma unroll
            for (int p = 0; p < 4; p++)
                FMA2(acc[jj][p], xp[p], wp[jj]);
    }

#pragma unroll
    for (int p = 0; p < 4; p++) {
        int rowlo = br + r0 + (p < 2 ? 2 * p : 60 + 2 * p);
        float lo0, hi0, lo1, hi1;
        UNPACK2(lo0, hi0, acc[0][p]);
        UNPACK2(lo1, hi1, acc[1][p]);
        if (rowlo < n)
            Out[(size_t)rowlo * 16 + jg] = __floats2half2_rn(lo0, lo1);
        if (rowlo + 1 < n)
            Out[(size_t)(rowlo + 1) * 16 + jg] = __floats2half2_rn(hi0, hi1);
    }
}

// ===================== CSR pull aggregation (fp16 rows in, fp32 math) ======
// TPN threads per node; features = TPN*8. Each thread owns one uint4 (8 halfs).
template <int TPN, bool RELU, bool OUTH>
__global__ void __launch_bounds__(256) k_pullh(
    const __half2* __restrict__ HW, const float* __restrict__ bias,
    float* __restrict__ OutF, __half2* __restrict__ OutH, int n)
{
    const int t = threadIdx.x;
    const int v = blockIdx.x * (256 / TPN) + t / TPN;
    const int j = t % TPN;
    if (v >= n) return;

    const int s0 = g_start[v];
    const int s1 = s0 + g_cnt[v];
    const uint4* HW4 = (const uint4*)HW;   // one uint4 = 8 halfs; row = TPN uint4

    float acc[8];
#pragma unroll
    for (int i = 0; i < 8; i++) acc[i] = 0.f;

    for (int k = s0; k < s1; k++) {
        int r = g_adj[k];
        float w = g_dinv[r];
        uint4 raw = HW4[(size_t)r * TPN + j];
        float2 f0 = __half22float2(*(__half2*)&raw.x);
        float2 f1 = __half22float2(*(__half2*)&raw.y);
        float2 f2 = __half22float2(*(__half2*)&raw.z);
        float2 f3 = __half22float2(*(__half2*)&raw.w);
        acc[0] = fmaf(w, f0.x, acc[0]); acc[1] = fmaf(w, f0.y, acc[1]);
        acc[2] = fmaf(w, f1.x, acc[2]); acc[3] = fmaf(w, f1.y, acc[3]);
        acc[4] = fmaf(w, f2.x, acc[4]); acc[5] = fmaf(w, f2.y, acc[5]);
        acc[6] = fmaf(w, f3.x, acc[6]); acc[7] = fmaf(w, f3.y, acc[7]);
    }

    float dv = g_dinv[v];
    float sl = dv * dv;
    uint4 raw = HW4[(size_t)v * TPN + j];
    float2 s0f = __half22float2(*(__half2*)&raw.x);
    float2 s1f = __half22float2(*(__half2*)&raw.y);
    float2 s2f = __half22float2(*(__half2*)&raw.z);
    float2 s3f = __half22float2(*(__half2*)&raw.w);
    float slf[8] = {s0f.x, s0f.y, s1f.x, s1f.y, s2f.x, s2f.y, s3f.x, s3f.y};

    float o[8];
#pragma unroll
    for (int i = 0; i < 8; i++) {
        o[i] = fmaf(dv, acc[i], fmaf(sl, slf[i], bias[j * 8 + i]));
        if (RELU) o[i] = fmaxf(o[i], 0.f);
    }

    if (OUTH) {
        uint4 u;
        *(__half2*)&u.x = __floats2half2_rn(o[0], o[1]);
        *(__half2*)&u.y = __floats2half2_rn(o[2], o[3]);
        *(__half2*)&u.z = __floats2half2_rn(o[4], o[5]);
        *(__half2*)&u.w = __floats2half2_rn(o[6], o[7]);
        ((uint4*)OutH)[(size_t)v * TPN + j] = u;
    } else {
        ((float4*)OutF)[(size_t)v * TPN * 2 + j * 2 + 0] = make_float4(o[0], o[1], o[2], o[3]);
        ((float4*)OutF)[(size_t)v * TPN * 2 + j * 2 + 1] = make_float4(o[4], o[5], o[6], o[7]);
    }
}

// -------- edge dot over fp16 z rows (32 feats = 4 uint4); 4 lanes/edge -----
__global__ void k_edot(const int* __restrict__ eli, float* __restrict__ out, int EL)
{
    int gid = blockIdx.x * blockDim.x + threadIdx.x;
    if (gid >= EL * 4) return;
    int e = gid >> 2;
    int j = gid & 3;
    int s = eli[e];
    int d = eli[EL + e];
    const uint4* Z = (const uint4*)g_zh;
    uint4 a = Z[(size_t)s * 4 + j];
    uint4 b = Z[(size_t)d * 4 + j];
    float p = 0.f;
    {
        float2 fa, fb;
        fa = __half22float2(*(__half2*)&a.x); fb = __half22float2(*(__half2*)&b.x);
        p = fmaf(fa.x, fb.x, p); p = fmaf(fa.y, fb.y, p);
        fa = __half22float2(*(__half2*)&a.y); fb = __half22float2(*(__half2*)&b.y);
        p = fmaf(fa.x, fb.x, p); p = fmaf(fa.y, fb.y, p);
        fa = __half22float2(*(__half2*)&a.z); fb = __half22float2(*(__half2*)&b.z);
        p = fmaf(fa.x, fb.x, p); p = fmaf(fa.y, fb.y, p);
        fa = __half22float2(*(__half2*)&a.w); fb = __half22float2(*(__half2*)&b.w);
        p = fmaf(fa.x, fb.x, p); p = fmaf(fa.y, fb.y, p);
    }
    p += __shfl_down_sync(0xffffffffu, p, 2);
    p += __shfl_down_sync(0xffffffffu, p, 1);
    if (j == 0) out[e] = p;
}

extern "C" void kernel_launch(void* const* d_in, const int* in_sizes, int n_in,
                              void* d_out, int out_size)
{
    (void)n_in; (void)out_size;
    const float* x   = (const float*)d_in[0];
    const int*   ei  = (const int*)  d_in[1];
    const int*   eli = (const int*)  d_in[2];
    const float* Wih = (const float*)d_in[3];
    const float* bih = (const float*)d_in[5];
    const float* bhh = (const float*)d_in[6];
    const float* W1  = (const float*)d_in[7];
    const float* b1  = (const float*)d_in[8];
    const float* W2  = (const float*)d_in[9];
    const float* b2  = (const float*)d_in[10];
    float* out = (float*)d_out;

    int n  = in_sizes[0] / 64;
    int E  = in_sizes[1] / 2;
    int EL = in_sizes[2] / 2;
    const int* row = ei;
    const int* col = ei + E;

    float *p_h;
    __half2 *p_hw1, *p_hw2, *p_z;
    cudaGetSymbolAddress((void**)&p_h,   g_h);
    cudaGetSymbolAddress((void**)&p_hw1, g_hw1h);
    cudaGetSymbolAddress((void**)&p_hw2, g_hw2h);
    cudaGetSymbolAddress((void**)&p_z,   g_zh);

    // Side stream + events, created once (outside any capture). Work per call
    // is identical; these are just handles.
    static cudaStream_t s2 = nullptr;
    static cudaEvent_t evFork = nullptr, evJoin = nullptr;
    if (s2 == nullptr) {
        cudaStreamCreateWithFlags(&s2, cudaStreamNonBlocking);
        cudaEventCreateWithFlags(&evFork, cudaEventDisableTiming);
        cudaEventCreateWithFlags(&evJoin, cudaEventDisableTiming);
    }

    const int T = 256;
    int nb = (n + 511) / 512;

    // ---- fork: CSR build on s2, LSTM chain on main stream ----
    cudaEventRecord(evFork, 0);
    cudaStreamWaitEvent(s2, evFork, 0);

    k_zero <<<(n + T - 1) / T, T, 0, s2>>>(n);
    k_cnt  <<<(E + T - 1) / T, T, 0, s2>>>(col, E);
    k_scan1<<<nb, 512, 0, s2>>>(n);
    k_scan2<<<1, 256, 0, s2>>>(nb);
    k_scan3<<<(n + T - 1) / T, T, 0, s2>>>(n);
    k_fill <<<(E + T - 1) / T, T, 0, s2>>>(row, col, E);
    cudaEventRecord(evJoin, s2);

    k_lstm  <<<(n + 63) / 64, 256>>>(x, Wih, bih, bhh, n);
    k_gemm64<<<(n + 63) / 64, 128>>>(p_h, W1, p_hw1, n);

    // ---- join ----
    cudaStreamWaitEvent(0, evJoin, 0);

    k_pullh<8, true,  false><<<(n * 8 + T - 1) / T, T>>>(p_hw1, b1, p_h, nullptr, n);
    k_gemm32<<<(n + 127) / 128, 256>>>(p_h, W2, p_hw2, n);
    k_pullh<4, false, true ><<<(n * 4 + T - 1) / T, T>>>(p_hw2, b2, nullptr, p_z, n);
    k_edot<<<(EL * 4 + T - 1) / T, T>>>(eli, out, EL);
}